// round 12
// baseline (speedup 1.0000x reference)
#include <cuda_runtime.h>
#include <cstdint>

// ---------------------------------------------------------------------------
// logits = (mean of 5 inverted-dropout passes of x) @ W^T + b
//   x: [32, 2048, 1024] f32   W: [3, 1024] f32   b: [3] f32   out: [32,2048,3]
//
// Dropout masks reproduce JAX threefry2x32 with jax_threefry_partitionable=True
// (default in modern JAX):
//   split(key(42), 5): child key j = (out.x0, out.x1) of threefry block with
//     key data (0, 42) and counter (hi, lo) = (0, j).
//   random_bits(k, 32, shape): element flat index i gets
//     bits = out.x0 XOR out.x1 of threefry block with key k, counter (0, i).
//   bernoulli(k, 1-p): keep <=> ((0x3F800000 | bits>>9) as f32) - 1 < f32(1-p)
//     <=> bits < (ceil(f32(1-p) * 2^23) << 9)  as unsigned compare.
// ---------------------------------------------------------------------------

#define NUM_D 1024
#define NUM_ROWS 65536   /* 32 * 2048 */

struct U2 { unsigned a, b; };

__host__ __device__ constexpr unsigned rotl32c(unsigned v, int d) {
    return (v << d) | (v >> (32 - d));
}

// constexpr threefry2x32 (20 rounds) — JAX-exact key schedule.
constexpr U2 tf_const(unsigned k0, unsigned k1, unsigned x0, unsigned x1) {
    unsigned ks0 = k0, ks1 = k1, ks2 = k0 ^ k1 ^ 0x1BD11BDAu;
    x0 += ks0; x1 += ks1;
    const int RA[4] = {13, 15, 26, 6};
    const int RB[4] = {17, 29, 16, 24};
    for (int g = 0; g < 5; ++g) {
        const int* R = (g % 2 == 0) ? RA : RB;
        for (int i = 0; i < 4; ++i) {
            x0 += x1; x1 = rotl32c(x1, R[i]); x1 ^= x0;
        }
        switch (g) {
            case 0: x0 += ks1; x1 += ks2 + 1u; break;
            case 1: x0 += ks2; x1 += ks0 + 2u; break;
            case 2: x0 += ks0; x1 += ks1 + 3u; break;
            case 3: x0 += ks1; x1 += ks2 + 4u; break;
            case 4: x0 += ks2; x1 += ks0 + 5u; break;
        }
    }
    return {x0, x1};
}

// Partitionable split: child key j = full block output, counter (0, j).
constexpr U2 KEY0 = tf_const(0u, 42u, 0u, 0u);   // p = 0.1
constexpr U2 KEY1 = tf_const(0u, 42u, 0u, 1u);   // p = 0.2
constexpr U2 KEY2 = tf_const(0u, 42u, 0u, 2u);   // p = 0.3
constexpr U2 KEY3 = tf_const(0u, 42u, 0u, 3u);   // p = 0.4
constexpr U2 KEY4 = tf_const(0u, 42u, 0u, 4u);   // p = 0.5

// keep <=> bits < thresh  (unsigned), exact float32 uniform-compare equivalent
constexpr unsigned thresh_bits(double p) {
    float cf = (float)(1.0 - p);
    double v = (double)cf * 8388608.0;   // * 2^23
    unsigned t = (unsigned)v;
    if ((double)t < v) t += 1u;
    return t << 9;
}
constexpr unsigned TA = thresh_bits(0.1);
constexpr unsigned TB = thresh_bits(0.2);
constexpr unsigned TC = thresh_bits(0.3);
constexpr unsigned TD = thresh_bits(0.4);
constexpr unsigned TE = thresh_bits(0.5);

// per-kept-mask contribution: (1/float32(1-p)) / 5
constexpr float inv5(double p) {
    return (float)(0.2 / (double)((float)(1.0 - p)));
}
constexpr float IA = inv5(0.1);
constexpr float IB = inv5(0.2);
constexpr float IC = inv5(0.3);
constexpr float ID = inv5(0.4);
constexpr float IE = inv5(0.5);

// Device threefry2x32 block with counter (0, i); returns x0_out ^ x1_out
// (partitionable 32-bit random_bits combine). Rotations via funnel shift.
__device__ __forceinline__ unsigned tf_xor(unsigned ks0, unsigned ks1, unsigned i) {
    unsigned ks2 = ks0 ^ ks1 ^ 0x1BD11BDAu;
    unsigned x0 = ks0;          // hi counter = 0
    unsigned x1 = i + ks1;      // lo counter = flat element index
#define TF_RND(d) { x0 += x1; x1 = __funnelshift_l(x1, x1, (d)); x1 ^= x0; }
    TF_RND(13) TF_RND(15) TF_RND(26) TF_RND(6)
    x0 += ks1; x1 += ks2 + 1u;
    TF_RND(17) TF_RND(29) TF_RND(16) TF_RND(24)
    x0 += ks2; x1 += ks0 + 2u;
    TF_RND(13) TF_RND(15) TF_RND(26) TF_RND(6)
    x0 += ks0; x1 += ks1 + 3u;
    TF_RND(17) TF_RND(29) TF_RND(16) TF_RND(24)
    x0 += ks1; x1 += ks2 + 4u;
    TF_RND(13) TF_RND(15) TF_RND(26) TF_RND(6)
    x0 += ks2; x1 += ks0 + 5u;
#undef TF_RND
    return x0 ^ x1;
}

// One CTA per (b,s) row. 256 threads, 4 columns per thread.
// Per column: 5 independent threefry chains (ILP=5), integer compare masks,
// fused scale + 3-output GEMV accumulation.
__global__ void __launch_bounds__(256)
nbme_head_kernel(const float* __restrict__ x,
                 const float* __restrict__ W,
                 const float* __restrict__ bias,
                 float* __restrict__ out) {
    const unsigned r   = blockIdx.x;        // 0 .. 65535
    const unsigned tid = threadIdx.x;

    const float* __restrict__ xr = x + (size_t)r * NUM_D;
    const unsigned base_idx = r * (unsigned)NUM_D;   // flat index < 2^26

    float a0 = 0.f, a1 = 0.f, a2 = 0.f;

#pragma unroll 1
    for (int k = 0; k < 4; ++k) {
        const unsigned c = tid + (unsigned)k * 256u;

        // loads issued first — overlap with the long integer chains
        const float xv = xr[c];
        const float w0 = __ldg(&W[c]);
        const float w1 = __ldg(&W[NUM_D + c]);
        const float w2 = __ldg(&W[2 * NUM_D + c]);

        const unsigned i = base_idx + c;

        const unsigned ma = tf_xor(KEY0.a, KEY0.b, i);
        const unsigned mb = tf_xor(KEY1.a, KEY1.b, i);
        const unsigned mc = tf_xor(KEY2.a, KEY2.b, i);
        const unsigned md = tf_xor(KEY3.a, KEY3.b, i);
        const unsigned me = tf_xor(KEY4.a, KEY4.b, i);

        float s = 0.f;
        if (ma < TA) s += IA;
        if (mb < TB) s += IB;
        if (mc < TC) s += IC;
        if (md < TD) s += ID;
        if (me < TE) s += IE;

        const float xs = xv * s;
        a0 = fmaf(xs, w0, a0);
        a1 = fmaf(xs, w1, a1);
        a2 = fmaf(xs, w2, a2);
    }

    // --- block reduction: 3 partial dots ---
    float vals[3] = {a0, a1, a2};
#pragma unroll
    for (int o = 0; o < 3; ++o) {
#pragma unroll
        for (int s = 16; s > 0; s >>= 1)
            vals[o] += __shfl_xor_sync(0xffffffffu, vals[o], s);
    }

    __shared__ float red[8][3];
    const unsigned warp = tid >> 5, lane = tid & 31;
    if (lane == 0) {
#pragma unroll
        for (int o = 0; o < 3; ++o) red[warp][o] = vals[o];
    }
    __syncthreads();

    if (tid < 3) {
        float v = 0.f;
#pragma unroll
        for (int w = 0; w < 8; ++w) v += red[w][tid];
        out[(size_t)r * 3 + tid] = v + __ldg(&bias[tid]);
    }
}

extern "C" void kernel_launch(void* const* d_in, const int* in_sizes, int n_in,
                              void* d_out, int out_size) {
    (void)in_sizes; (void)n_in; (void)out_size;
    const float* x  = (const float*)d_in[0];  // [32,2048,1024]
    const float* W  = (const float*)d_in[1];  // [3,1024]
    const float* b  = (const float*)d_in[2];  // [3]
    float* out      = (float*)d_out;          // [32,2048,3]

    nbme_head_kernel<<<NUM_ROWS, 256>>>(x, W, b, out);
}